// round 14
// baseline (speedup 1.0000x reference)
#include <cuda_runtime.h>
#include <cstdint>

// ---------------- problem constants ----------------
#define BNT   8192      // B*N nodes
#define CCH   256       // channels
#define BB    8
#define NNODE 1024
#define HH    8
#define DKK   32
#define EE    131072
#define C2    512
#define EPSB  1e-5f

// ---------------- device scratch ----------------
__device__ float g_xWn [BNT*CCH];
__device__ float g_q   [BNT*CCH];
__device__ float g_k   [BNT*CCH];
__device__ float g_v   [BNT*CCH];
__device__ float g_agg [BNT*CCH];   // h1 = x@Wr + x + segsum
__device__ float g_o   [BNT*CCH];
__device__ float g_h2  [BNT*CCH];
__device__ float g_out0[BNT*CCH];
__device__ float g_hid [BNT*C2];
__device__ float g_out1[BNT*CCH];
__device__ float g_ssum[3][CCH];
__device__ float g_ssq [3][CCH];

// ---------------- zero stats ----------------
__global__ void zero_stats_kernel() {
    int c = threadIdx.x;
    #pragma unroll
    for (int s = 0; s < 3; s++) { g_ssum[s][c] = 0.f; g_ssq[s][c] = 0.f; }
}

// =======================================================================
// tf32 tensor-core GEMM: 128x128 block, BK=16, 256 threads (8 warps),
// warp tile 64x32 = 4x4 m16n8k8 mma. Double-buffered smem.
// Optional fused column stats (sum, sumsq) via shfl-reduce + atomics.
// =======================================================================
#define TAPAD 20
#define TBPAD 136

__device__ __forceinline__ uint32_t f2tf(float x) {
    uint32_t y;
    asm volatile("cvt.rna.tf32.f32 %0, %1;" : "=r"(y) : "f"(x));
    return y;
}

__device__ __forceinline__ uint32_t bf2(float lo, float hi) {
    uint32_t r;
    asm volatile("cvt.rn.bf16x2.f32 %0, %1, %2;" : "=r"(r) : "f"(hi), "f"(lo));
    return r;
}

__device__ __forceinline__ void mma8(float* d, const uint32_t* a, const uint32_t* b) {
    asm volatile(
        "mma.sync.aligned.m16n8k8.row.col.f32.tf32.tf32.f32 "
        "{%0,%1,%2,%3}, {%4,%5,%6,%7}, {%8,%9}, {%0,%1,%2,%3};\n"
        : "+f"(d[0]), "+f"(d[1]), "+f"(d[2]), "+f"(d[3])
        : "r"(a[0]), "r"(a[1]), "r"(a[2]), "r"(a[3]),
          "r"(b[0]), "r"(b[1]));
}

__device__ __forceinline__ void mma16bf(float* d, const uint32_t* a, const uint32_t* b) {
    asm volatile(
        "mma.sync.aligned.m16n8k16.row.col.f32.bf16.bf16.f32 "
        "{%0,%1,%2,%3}, {%4,%5,%6,%7}, {%8,%9}, {%0,%1,%2,%3};\n"
        : "+f"(d[0]), "+f"(d[1]), "+f"(d[2]), "+f"(d[3])
        : "r"(a[0]), "r"(a[1]), "r"(a[2]), "r"(a[3]),
          "r"(b[0]), "r"(b[1]));
}

__device__ __forceinline__ void mma_gemm_core(
    const float* __restrict__ A, const float* __restrict__ Bm,
    const float* __restrict__ bias, const float* __restrict__ res,
    float* __restrict__ Cc, int N, int K, int block_row, int block_col, int relu,
    float* __restrict__ ssum, float* __restrict__ ssq,
    uint32_t (*As)[128][TAPAD], uint32_t (*Bs)[16][TBPAD])
{
    const int tid  = threadIdx.x;
    const int lane = tid & 31;
    const int w    = tid >> 5;
    const int wm   = (w >> 2) * 64;
    const int wn   = (w & 3) * 32;
    const int qr   = lane >> 2;
    const int qc   = lane & 3;

    const int aRow = tid >> 1;
    const int aK   = (tid & 1) * 8;
    const int bRow = tid >> 4;
    const int bCol = (tid & 15) * 8;

    const float* Aptr = A + (size_t)(block_row*128) * K;
    const float* Bptr = Bm + block_col*128;

    float acc[4][4][4];
    #pragma unroll
    for (int mi = 0; mi < 4; mi++)
        #pragma unroll
        for (int ni = 0; ni < 4; ni++)
            #pragma unroll
            for (int r = 0; r < 4; r++) acc[mi][ni][r] = 0.f;

    const int nstages = K >> 4;
    float4 ra0, ra1, rb0, rb1;

    ra0 = *(const float4*)(Aptr + (size_t)aRow*K + aK);
    ra1 = *(const float4*)(Aptr + (size_t)aRow*K + aK + 4);
    rb0 = *(const float4*)(Bptr + (size_t)bRow*N + bCol);
    rb1 = *(const float4*)(Bptr + (size_t)bRow*N + bCol + 4);
    {
        uint4 u;
        u.x = f2tf(ra0.x); u.y = f2tf(ra0.y); u.z = f2tf(ra0.z); u.w = f2tf(ra0.w);
        *(uint4*)&As[0][aRow][aK] = u;
        u.x = f2tf(ra1.x); u.y = f2tf(ra1.y); u.z = f2tf(ra1.z); u.w = f2tf(ra1.w);
        *(uint4*)&As[0][aRow][aK + 4] = u;
        u.x = f2tf(rb0.x); u.y = f2tf(rb0.y); u.z = f2tf(rb0.z); u.w = f2tf(rb0.w);
        *(uint4*)&Bs[0][bRow][bCol] = u;
        u.x = f2tf(rb1.x); u.y = f2tf(rb1.y); u.z = f2tf(rb1.z); u.w = f2tf(rb1.w);
        *(uint4*)&Bs[0][bRow][bCol + 4] = u;
    }
    __syncthreads();

    for (int s = 0; s < nstages; s++) {
        const int buf = s & 1;
        const bool more = (s + 1 < nstages);
        if (more) {
            int k0 = (s + 1) << 4;
            ra0 = *(const float4*)(Aptr + (size_t)aRow*K + k0 + aK);
            ra1 = *(const float4*)(Aptr + (size_t)aRow*K + k0 + aK + 4);
            rb0 = *(const float4*)(Bptr + (size_t)(k0 + bRow)*N + bCol);
            rb1 = *(const float4*)(Bptr + (size_t)(k0 + bRow)*N + bCol + 4);
        }

        #pragma unroll
        for (int ks = 0; ks < 2; ks++) {
            const int kk = ks * 8;
            uint32_t af[4][4], bf[4][2];
            #pragma unroll
            for (int mi = 0; mi < 4; mi++) {
                int m = wm + mi*16 + qr;
                af[mi][0] = As[buf][m    ][kk + qc];
                af[mi][1] = As[buf][m + 8][kk + qc];
                af[mi][2] = As[buf][m    ][kk + qc + 4];
                af[mi][3] = As[buf][m + 8][kk + qc + 4];
            }
            #pragma unroll
            for (int ni = 0; ni < 4; ni++) {
                int n = wn + ni*8 + qr;
                bf[ni][0] = Bs[buf][kk + qc    ][n];
                bf[ni][1] = Bs[buf][kk + qc + 4][n];
            }
            #pragma unroll
            for (int mi = 0; mi < 4; mi++)
                #pragma unroll
                for (int ni = 0; ni < 4; ni++)
                    mma8(acc[mi][ni], af[mi], bf[ni]);
        }

        if (more) {
            const int nb = buf ^ 1;
            uint4 u;
            u.x = f2tf(ra0.x); u.y = f2tf(ra0.y); u.z = f2tf(ra0.z); u.w = f2tf(ra0.w);
            *(uint4*)&As[nb][aRow][aK] = u;
            u.x = f2tf(ra1.x); u.y = f2tf(ra1.y); u.z = f2tf(ra1.z); u.w = f2tf(ra1.w);
            *(uint4*)&As[nb][aRow][aK + 4] = u;
            u.x = f2tf(rb0.x); u.y = f2tf(rb0.y); u.z = f2tf(rb0.z); u.w = f2tf(rb0.w);
            *(uint4*)&Bs[nb][bRow][bCol] = u;
            u.x = f2tf(rb1.x); u.y = f2tf(rb1.y); u.z = f2tf(rb1.z); u.w = f2tf(rb1.w);
            *(uint4*)&Bs[nb][bRow][bCol + 4] = u;
        }
        __syncthreads();
    }

    const int row0 = block_row*128 + wm;
    const int col0 = block_col*128 + wn;

    float cs[4][2], cq[4][2];
    #pragma unroll
    for (int ni = 0; ni < 4; ni++) {
        cs[ni][0] = cs[ni][1] = 0.f;
        cq[ni][0] = cq[ni][1] = 0.f;
    }

    #pragma unroll
    for (int mi = 0; mi < 4; mi++) {
        #pragma unroll
        for (int half = 0; half < 2; half++) {
            const int r = row0 + mi*16 + qr + half*8;
            #pragma unroll
            for (int ni = 0; ni < 4; ni++) {
                const int c = col0 + ni*8 + 2*qc;
                float v0 = acc[mi][ni][half*2 + 0];
                float v1 = acc[mi][ni][half*2 + 1];
                if (bias) { v0 += bias[c]; v1 += bias[c+1]; }
                if (res) {
                    float2 rv = *(const float2*)(res + (size_t)r*N + c);
                    v0 += rv.x; v1 += rv.y;
                }
                if (relu) { v0 = fmaxf(v0, 0.f); v1 = fmaxf(v1, 0.f); }
                if (ssum) {
                    cs[ni][0] += v0; cs[ni][1] += v1;
                    cq[ni][0] += v0*v0; cq[ni][1] += v1*v1;
                }
                *(float2*)(Cc + (size_t)r*N + c) = make_float2(v0, v1);
            }
        }
    }

    if (ssum) {
        #pragma unroll
        for (int ni = 0; ni < 4; ni++) {
            #pragma unroll
            for (int e = 0; e < 2; e++) {
                float s = cs[ni][e], q = cq[ni][e];
                #pragma unroll
                for (int off = 4; off < 32; off <<= 1) {
                    s += __shfl_xor_sync(0xffffffffu, s, off);
                    q += __shfl_xor_sync(0xffffffffu, q, off);
                }
                if (qr == 0) {
                    int c = col0 + ni*8 + 2*qc + e;
                    atomicAdd(&ssum[c], s);
                    atomicAdd(&ssq[c], q);
                }
            }
        }
    }
}

// ---------------- generic GEMM (Wo, MLP) ----------------
__global__ __launch_bounds__(256, 2)
void sgemm_kernel(const float* __restrict__ A, const float* __restrict__ Bm,
                  const float* __restrict__ bias, const float* __restrict__ res,
                  float* __restrict__ Cc, int N, int K, int relu,
                  float* ssum, float* ssq)
{
    __shared__ uint32_t As[2][128][TAPAD];
    __shared__ uint32_t Bs[2][16][TBPAD];
    mma_gemm_core(A, Bm, bias, res, Cc, N, K, blockIdx.y, blockIdx.x, relu,
                  ssum, ssq, As, Bs);
}

// ---------------- merged 5-way projection GEMM ----------------
struct P5 {
    const float* B[5];
    const float* bias[5];
    const float* res[5];
    float*       C[5];
};

__global__ __launch_bounds__(256, 2)
void proj_gemm_kernel(const float* __restrict__ A, P5 p)
{
    __shared__ uint32_t As[2][128][TAPAD];
    __shared__ uint32_t Bs[2][16][TBPAD];
    const int bw = blockIdx.x >> 1;
    const int bc = blockIdx.x & 1;
    mma_gemm_core(A, p.B[bw], p.bias[bw], p.res[bw], p.C[bw],
                  CCH, CCH, blockIdx.y, bc, 0, nullptr, nullptr, As, Bs);
}

// ---------------- edge scatter: agg[dst] += xWn[src] (vector red) ------
__global__ void scatter_kernel(const int* __restrict__ ei) {
    int t = blockIdx.x * blockDim.x + threadIdx.x;
    if (t >= EE*64) return;
    int e = t >> 6;
    int j = (t & 63) * 4;
    int src = ei[e];
    int dst = ei[EE + e];
    float4 mv = *(const float4*)(g_xWn + (size_t)src*CCH + j);
    float* p = g_agg + (size_t)dst*CCH + j;
    asm volatile("red.global.add.v4.f32 [%0], {%1,%2,%3,%4};"
                 :: "l"(p), "f"(mv.x), "f"(mv.y), "f"(mv.z), "f"(mv.w)
                 : "memory");
}

// ---------------- per-column stats (h1 = agg) -> slot 0 ----------------
__global__ void colstats_kernel(const float* __restrict__ X,
                                float* __restrict__ ssum, float* __restrict__ ssq) {
    int c = threadIdx.x;
    size_t r0 = (size_t)blockIdx.x * 16;
    float s = 0.f, q = 0.f;
    #pragma unroll
    for (int rr = 0; rr < 16; rr++) {
        float v = X[(r0 + rr)*CCH + c];
        s += v; q += v * v;
    }
    atomicAdd(&ssum[c], s);
    atomicAdd(&ssq[c], q);
}

// =======================================================================
// Attention: S = Q K^T (tf32 mma, Q a-frags hoisted in regs), P kept in
// registers (c-layout == bf16 a-layout), PV via bf16 m16n8k16 mma.
// No smem transpose of P, no cross-warp reductions. 2 syncs/chunk.
// grid: (N/128, H, B), 256 threads (8 warps, 16 q-rows each).
// =======================================================================
#define KB_WORDS (32*66)    // K b-frags (tf32): [8 ni * 4 ks][lane*2 + e]
#define VB_WORDS (16*66)    // V b-frags (bf16x2): [4 nf * 4 k16][lane*2 + reg]

__global__ __launch_bounds__(256, 2)
void attn_mma_kernel(const float* __restrict__ sph) {
    __shared__ uint32_t KB[KB_WORDS];
    __shared__ uint32_t VB[VB_WORDS];

    const int i0   = blockIdx.x * 128;
    const int h    = blockIdx.y;
    const int b    = blockIdx.z;
    const int tid  = threadIdx.x;
    const int lane = tid & 31;
    const int w    = tid >> 5;
    const int qr   = lane >> 2;
    const int qc   = lane & 3;
    const int m0   = w * 16;

    const size_t base = (size_t)b*NNODE*CCH + h*DKK;
    const float rscale = 0.17677669529663688f;  // 1/sqrt(32)

    // ---- hoist Q a-fragments (chunk-invariant) ----
    const float* q0 = g_q + base + (size_t)(i0 + m0 + qr)*CCH;      // row qr
    const float* q8 = q0 + 8*CCH;                                    // row qr+8
    uint32_t qa[4][4];
    #pragma unroll
    for (int ks = 0; ks < 4; ks++) {
        qa[ks][0] = f2tf(q0[ks*8 + qc]);
        qa[ks][1] = f2tf(q8[ks*8 + qc]);
        qa[ks][2] = f2tf(q0[ks*8 + qc + 4]);
        qa[ks][3] = f2tf(q8[ks*8 + qc + 4]);
    }

    float oc[4][4];
    #pragma unroll
    for (int a = 0; a < 4; a++)
        #pragma unroll
        for (int r = 0; r < 4; r++) oc[a][r] = 0.f;
    float rs0 = 0.f, rs1 = 0.f;

    const float* sph0 = sph + ((size_t)b*NNODE + i0 + m0 + qr)*NNODE;
    const float* sph8 = sph0 + 8*NNODE;

    // K pack slice: 64 rows * 8 groups = 512 / 256 threads = 2 reps
    // V pack slice: 32 row-pairs * 8 groups = 256 = 1 rep
    for (int jt = 0; jt < NNODE; jt += 64) {
        // ---- pack K (tf32 b-frags) and V (bf16x2 b-frags) ----
        #pragma unroll
        for (int rep = 0; rep < 2; rep++) {
            int idx = tid + rep*256;
            int j = idx >> 3, c4 = (idx & 7) * 4;
            float4 kv = *(const float4*)(g_k + base + (size_t)(jt + j)*CCH + c4);
            int ni = j >> 3, qrb = j & 7;
            int ks = c4 >> 3, e = (c4 >> 2) & 1;
            int wbase = (ni*4 + ks)*66 + e;
            KB[wbase + (qrb*4 + 0)*2] = f2tf(kv.x);
            KB[wbase + (qrb*4 + 1)*2] = f2tf(kv.y);
            KB[wbase + (qrb*4 + 2)*2] = f2tf(kv.z);
            KB[wbase + (qrb*4 + 3)*2] = f2tf(kv.w);
        }
        {
            int jp = tid >> 3, c4 = (tid & 7) * 4;
            float4 v0 = *(const float4*)(g_v + base + (size_t)(jt + 2*jp    )*CCH + c4);
            float4 v1 = *(const float4*)(g_v + base + (size_t)(jt + 2*jp + 1)*CCH + c4);
            int ksv = jp >> 3, reg = (jp >> 2) & 1, qcv = jp & 3;
            int nf = c4 >> 3, qv0 = c4 & 7;
            int wbase = (nf*4 + ksv)*66 + reg;
            VB[wbase + ((qv0 + 0)*4 + qcv)*2] = bf2(v0.x, v1.x);
            VB[wbase + ((qv0 + 1)*4 + qcv)*2] = bf2(v0.y, v1.y);
            VB[wbase + ((qv0 + 2)*4 + qcv)*2] = bf2(v0.z, v1.z);
            VB[wbase + ((qv0 + 3)*4 + qcv)*2] = bf2(v0.w, v1.w);
        }
        __syncthreads();

        // ---- S = Q K^T (tf32) ----
        float sc[8][4];
        #pragma unroll
        for (int ni = 0; ni < 8; ni++)
            #pragma unroll
            for (int r = 0; r < 4; r++) sc[ni][r] = 0.f;

        #pragma unroll
        for (int ks = 0; ks < 4; ks++) {
            #pragma unroll
            for (int ni = 0; ni < 8; ni++) {
                uint2 bfv = *(const uint2*)&KB[(ni*4 + ks)*66 + lane*2];
                uint32_t bf[2] = {bfv.x, bfv.y};
                mma8(sc[ni], qa[ks], bf);
            }
        }

        // ---- exp(sc * rscale * sph) in registers -> bf16x2 a-frags ----
        uint32_t pe[8][2];
        #pragma unroll
        for (int ni = 0; ni < 8; ni++) {
            float2 s0 = *(const float2*)(sph0 + jt + ni*8 + 2*qc);
            float2 s1 = *(const float2*)(sph8 + jt + ni*8 + 2*qc);
            float p0 = __expf(sc[ni][0] * rscale * s0.x);
            float p1 = __expf(sc[ni][1] * rscale * s0.y);
            float p2 = __expf(sc[ni][2] * rscale * s1.x);
            float p3 = __expf(sc[ni][3] * rscale * s1.y);
            rs0 += p0 + p1;
            rs1 += p2 + p3;
            pe[ni][0] = bf2(p0, p1);
            pe[ni][1] = bf2(p2, p3);
        }

        // ---- O += P V (bf16 m16n8k16) ----
        #pragma unroll
        for (int k16 = 0; k16 < 4; k16++) {
            uint32_t af[4] = { pe[2*k16][0], pe[2*k16][1],
                               pe[2*k16+1][0], pe[2*k16+1][1] };
            #pragma unroll
            for (int nf = 0; nf < 4; nf++) {
                uint2 bfv = *(const uint2*)&VB[(nf*4 + k16)*66 + lane*2];
                uint32_t bf[2] = {bfv.x, bfv.y};
                mma16bf(oc[nf], af, bf);
            }
        }
        __syncthreads();   // KB/VB free for next chunk's pack
    }

    // ---- rowsum reduce over the 4 qc lanes (full row within warp) ----
    rs0 += __shfl_xor_sync(0xffffffffu, rs0, 1);
    rs0 += __shfl_xor_sync(0xffffffffu, rs0, 2);
    rs1 += __shfl_xor_sync(0xffffffffu, rs1, 1);
    rs1 += __shfl_xor_sync(0xffffffffu, rs1, 2);
    const float inv0 = 1.f / rs0;
    const float inv1 = 1.f / rs1;

    // ---- write O (c-layout) ----
    float* o0 = g_o + base + (size_t)(i0 + m0 + qr)*CCH;
    float* o8 = o0 + 8*CCH;
    #pragma unroll
    for (int nf = 0; nf < 4; nf++) {
        const int d = nf*8 + 2*qc;
        *(float2*)(o0 + d) = make_float2(oc[nf][0]*inv0, oc[nf][1]*inv0);
        *(float2*)(o8 + d) = make_float2(oc[nf][2]*inv1, oc[nf][3]*inv1);
    }
}

// ---------------- out0 = BN1(h1=agg) + BN2(h2) ----------------
__global__ void bn_combine_kernel(const float* __restrict__ ga1, const float* __restrict__ be1,
                                  const float* __restrict__ ga2, const float* __restrict__ be2) {
    int idx = blockIdx.x * blockDim.x + threadIdx.x;
    if (idx >= BNT*CCH/4) return;
    int c0 = (idx << 2) & (CCH - 1);
    float4 a = ((const float4*)g_agg)[idx];
    float4 bb = ((const float4*)g_h2)[idx];
    float av[4] = {a.x, a.y, a.z, a.w};
    float bv[4] = {bb.x, bb.y, bb.z, bb.w};
    float ov[4];
    const float inv_n = 1.f / (float)BNT;
    #pragma unroll
    for (int j = 0; j < 4; j++) {
        int c = c0 + j;
        float m1 = g_ssum[0][c] * inv_n;
        float v1 = g_ssq[0][c] * inv_n - m1*m1;
        float i1 = rsqrtf(v1 + EPSB);
        float m2 = g_ssum[1][c] * inv_n;
        float v2 = g_ssq[1][c] * inv_n - m2*m2;
        float i2 = rsqrtf(v2 + EPSB);
        ov[j] = (av[j]-m1)*i1*ga1[c] + be1[c] + (bv[j]-m2)*i2*ga2[c] + be2[c];
    }
    ((float4*)g_out0)[idx] = make_float4(ov[0], ov[1], ov[2], ov[3]);
}

// ---------------- final BN3 -> output ----------------
__global__ void bn_final_kernel(const float* __restrict__ ga3, const float* __restrict__ be3,
                                float* __restrict__ out) {
    int idx = blockIdx.x * blockDim.x + threadIdx.x;
    if (idx >= BNT*CCH/4) return;
    int c0 = (idx << 2) & (CCH - 1);
    float4 a = ((const float4*)g_out1)[idx];
    float av[4] = {a.x, a.y, a.z, a.w};
    float ov[4];
    const float inv_n = 1.f / (float)BNT;
    #pragma unroll
    for (int j = 0; j < 4; j++) {
        int c = c0 + j;
        float m3 = g_ssum[2][c] * inv_n;
        float v3 = g_ssq[2][c] * inv_n - m3*m3;
        float i3 = rsqrtf(v3 + EPSB);
        ov[j] = (av[j]-m3)*i3*ga3[c] + be3[c];
    }
    ((float4*)out)[idx] = make_float4(ov[0], ov[1], ov[2], ov[3]);
}

// ---------------- launcher ----------------
extern "C" void kernel_launch(void* const* d_in, const int* in_sizes, int n_in,
                              void* d_out, int out_size) {
    const float* x    = (const float*)d_in[0];
    const int*   eidx = (const int*)d_in[1];
    const float* sph  = (const float*)d_in[2];
    const float* Wr   = (const float*)d_in[3];
    const float* Wn   = (const float*)d_in[4];
    const float* Wq   = (const float*)d_in[5];
    const float* bq   = (const float*)d_in[6];
    const float* Wk   = (const float*)d_in[7];
    const float* bk   = (const float*)d_in[8];
    const float* Wv   = (const float*)d_in[9];
    const float* bv   = (const float*)d_in[10];
    const float* Wo   = (const float*)d_in[11];
    const float* bo   = (const float*)d_in[12];
    const float* W1   = (const float*)d_in[13];
    const float* b1   = (const float*)d_in[14];
    const float* W2   = (const float*)d_in[15];
    const float* b2   = (const float*)d_in[16];
    const float* ga1  = (const float*)d_in[17];
    const float* be1  = (const float*)d_in[18];
    const float* ga2  = (const float*)d_in[19];
    const float* be2  = (const float*)d_in[20];
    const float* ga3  = (const float*)d_in[21];
    const float* be3  = (const float*)d_in[22];
    float* out = (float*)d_out;

    float *p_xWn, *p_agg, *p_q, *p_k, *p_v, *p_o, *p_h2, *p_out0, *p_hid, *p_out1;
    float *p_ssum, *p_ssq;
    cudaGetSymbolAddress((void**)&p_xWn,  g_xWn);
    cudaGetSymbolAddress((void**)&p_agg,  g_agg);
    cudaGetSymbolAddress((void**)&p_q,    g_q);
    cudaGetSymbolAddress((void**)&p_k,    g_k);
    cudaGetSymbolAddress((void**)&p_v,    g_v);
    cudaGetSymbolAddress((void**)&p_o,    g_o);
    cudaGetSymbolAddress((void**)&p_h2,   g_h2);
    cudaGetSymbolAddress((void**)&p_out0, g_out0);
    cudaGetSymbolAddress((void**)&p_hid,  g_hid);
    cudaGetSymbolAddress((void**)&p_out1, g_out1);
    cudaGetSymbolAddress((void**)&p_ssum, g_ssum);
    cudaGetSymbolAddress((void**)&p_ssq,  g_ssq);

    const int elem4_blocks = (BNT*CCH/4 + 255) / 256;    // 2048

    zero_stats_kernel<<<1, 256>>>();

    // merged projections: xWn, agg(=x@Wr+x), q, k, v in one launch
    P5 p5;
    p5.B[0] = Wn; p5.B[1] = Wr; p5.B[2] = Wq; p5.B[3] = Wk; p5.B[4] = Wv;
    p5.bias[0] = nullptr; p5.bias[1] = nullptr;
    p5.bias[2] = bq; p5.bias[3] = bk; p5.bias[4] = bv;
    p5.res[0] = nullptr; p5.res[1] = x; p5.res[2] = nullptr;
    p5.res[3] = nullptr; p5.res[4] = nullptr;
    p5.C[0] = p_xWn; p5.C[1] = p_agg; p5.C[2] = p_q; p5.C[3] = p_k; p5.C[4] = p_v;
    proj_gemm_kernel<<<dim3(10, BNT/128), 256>>>(x, p5);

    // edge aggregation on top of x@Wr + x
    scatter_kernel<<<EE*64/256, 256>>>(eidx);

    // h1 stats (slot 0)
    colstats_kernel<<<BNT/16, 256>>>(p_agg, p_ssum + 0*CCH, p_ssq + 0*CCH);

    // branch 2: attention + output projection (+x residual, fused h2 stats slot 1)
    attn_mma_kernel<<<dim3(NNODE/128, HH, BB), 256>>>(sph);
    sgemm_kernel<<<dim3(CCH/128, BNT/128), 256>>>(p_o, Wo, bo, x, p_h2, CCH, CCH, 0,
                                                  p_ssum + 1*CCH, p_ssq + 1*CCH);

    // combine BN branches
    bn_combine_kernel<<<elem4_blocks, 256>>>(ga1, be1, ga2, be2);

    // MLP (W2 gemm fuses out1 stats slot 2)
    sgemm_kernel<<<dim3(C2/128, BNT/128), 256>>>(p_out0, W1, b1, nullptr, p_hid, C2, CCH, 1,
                                                 nullptr, nullptr);
    sgemm_kernel<<<dim3(CCH/128, BNT/128), 256>>>(p_hid, W2, b2, p_out0, p_out1, CCH, C2, 0,
                                                  p_ssum + 2*CCH, p_ssq + 2*CCH);

    // final BN
    bn_final_kernel<<<elem4_blocks, 256>>>(ga3, be3, out);
}

// round 15
// speedup vs baseline: 1.0050x; 1.0050x over previous
#include <cuda_runtime.h>
#include <cstdint>

// ---------------- problem constants ----------------
#define BNT   8192      // B*N nodes
#define CCH   256       // channels
#define BB    8
#define NNODE 1024
#define HH    8
#define DKK   32
#define EE    131072
#define C2    512
#define EPSB  1e-5f

// ---------------- device scratch ----------------
__device__ float g_xWn [BNT*CCH];
__device__ float g_q   [BNT*CCH];
__device__ float g_k   [BNT*CCH];
__device__ float g_v   [BNT*CCH];
__device__ float g_agg [BNT*CCH];   // h1 = x@Wr + x + segsum
__device__ float g_o   [BNT*CCH];
__device__ float g_h2  [BNT*CCH];
__device__ float g_out0[BNT*CCH];
__device__ float g_hid [BNT*C2];
__device__ float g_out1[BNT*CCH];
__device__ float g_ssum[3][CCH];
__device__ float g_ssq [3][CCH];

// ---------------- zero stats ----------------
__global__ void zero_stats_kernel() {
    int c = threadIdx.x;
    #pragma unroll
    for (int s = 0; s < 3; s++) { g_ssum[s][c] = 0.f; g_ssq[s][c] = 0.f; }
}

// =======================================================================
// tf32 tensor-core GEMM: 128x128 block, BK=16, 256 threads (8 warps),
// warp tile 64x32 = 4x4 m16n8k8 mma. Double-buffered smem.
// Optional fused column stats (sum, sumsq) via shfl-reduce + atomics.
// =======================================================================
#define TAPAD 20
#define TBPAD 136

__device__ __forceinline__ uint32_t f2tf(float x) {
    uint32_t y;
    asm volatile("cvt.rna.tf32.f32 %0, %1;" : "=r"(y) : "f"(x));
    return y;
}

__device__ __forceinline__ uint32_t bf2(float lo, float hi) {
    uint32_t r;
    asm volatile("cvt.rn.bf16x2.f32 %0, %1, %2;" : "=r"(r) : "f"(hi), "f"(lo));
    return r;
}

__device__ __forceinline__ void mma8(float* d, const uint32_t* a, const uint32_t* b) {
    asm volatile(
        "mma.sync.aligned.m16n8k8.row.col.f32.tf32.tf32.f32 "
        "{%0,%1,%2,%3}, {%4,%5,%6,%7}, {%8,%9}, {%0,%1,%2,%3};\n"
        : "+f"(d[0]), "+f"(d[1]), "+f"(d[2]), "+f"(d[3])
        : "r"(a[0]), "r"(a[1]), "r"(a[2]), "r"(a[3]),
          "r"(b[0]), "r"(b[1]));
}

__device__ __forceinline__ void mma16bf(float* d, const uint32_t* a, const uint32_t* b) {
    asm volatile(
        "mma.sync.aligned.m16n8k16.row.col.f32.bf16.bf16.f32 "
        "{%0,%1,%2,%3}, {%4,%5,%6,%7}, {%8,%9}, {%0,%1,%2,%3};\n"
        : "+f"(d[0]), "+f"(d[1]), "+f"(d[2]), "+f"(d[3])
        : "r"(a[0]), "r"(a[1]), "r"(a[2]), "r"(a[3]),
          "r"(b[0]), "r"(b[1]));
}

__device__ __forceinline__ void mma_gemm_core(
    const float* __restrict__ A, const float* __restrict__ Bm,
    const float* __restrict__ bias, const float* __restrict__ res,
    float* __restrict__ Cc, int N, int K, int block_row, int block_col, int relu,
    float* __restrict__ ssum, float* __restrict__ ssq,
    uint32_t (*As)[128][TAPAD], uint32_t (*Bs)[16][TBPAD])
{
    const int tid  = threadIdx.x;
    const int lane = tid & 31;
    const int w    = tid >> 5;
    const int wm   = (w >> 2) * 64;
    const int wn   = (w & 3) * 32;
    const int qr   = lane >> 2;
    const int qc   = lane & 3;

    const int aRow = tid >> 1;
    const int aK   = (tid & 1) * 8;
    const int bRow = tid >> 4;
    const int bCol = (tid & 15) * 8;

    const float* Aptr = A + (size_t)(block_row*128) * K;
    const float* Bptr = Bm + block_col*128;

    float acc[4][4][4];
    #pragma unroll
    for (int mi = 0; mi < 4; mi++)
        #pragma unroll
        for (int ni = 0; ni < 4; ni++)
            #pragma unroll
            for (int r = 0; r < 4; r++) acc[mi][ni][r] = 0.f;

    const int nstages = K >> 4;
    float4 ra0, ra1, rb0, rb1;

    ra0 = *(const float4*)(Aptr + (size_t)aRow*K + aK);
    ra1 = *(const float4*)(Aptr + (size_t)aRow*K + aK + 4);
    rb0 = *(const float4*)(Bptr + (size_t)bRow*N + bCol);
    rb1 = *(const float4*)(Bptr + (size_t)bRow*N + bCol + 4);
    {
        uint4 u;
        u.x = f2tf(ra0.x); u.y = f2tf(ra0.y); u.z = f2tf(ra0.z); u.w = f2tf(ra0.w);
        *(uint4*)&As[0][aRow][aK] = u;
        u.x = f2tf(ra1.x); u.y = f2tf(ra1.y); u.z = f2tf(ra1.z); u.w = f2tf(ra1.w);
        *(uint4*)&As[0][aRow][aK + 4] = u;
        u.x = f2tf(rb0.x); u.y = f2tf(rb0.y); u.z = f2tf(rb0.z); u.w = f2tf(rb0.w);
        *(uint4*)&Bs[0][bRow][bCol] = u;
        u.x = f2tf(rb1.x); u.y = f2tf(rb1.y); u.z = f2tf(rb1.z); u.w = f2tf(rb1.w);
        *(uint4*)&Bs[0][bRow][bCol + 4] = u;
    }
    __syncthreads();

    for (int s = 0; s < nstages; s++) {
        const int buf = s & 1;
        const bool more = (s + 1 < nstages);
        if (more) {
            int k0 = (s + 1) << 4;
            ra0 = *(const float4*)(Aptr + (size_t)aRow*K + k0 + aK);
            ra1 = *(const float4*)(Aptr + (size_t)aRow*K + k0 + aK + 4);
            rb0 = *(const float4*)(Bptr + (size_t)(k0 + bRow)*N + bCol);
            rb1 = *(const float4*)(Bptr + (size_t)(k0 + bRow)*N + bCol + 4);
        }

        #pragma unroll
        for (int ks = 0; ks < 2; ks++) {
            const int kk = ks * 8;
            uint32_t af[4][4], bf[4][2];
            #pragma unroll
            for (int mi = 0; mi < 4; mi++) {
                int m = wm + mi*16 + qr;
                af[mi][0] = As[buf][m    ][kk + qc];
                af[mi][1] = As[buf][m + 8][kk + qc];
                af[mi][2] = As[buf][m    ][kk + qc + 4];
                af[mi][3] = As[buf][m + 8][kk + qc + 4];
            }
            #pragma unroll
            for (int ni = 0; ni < 4; ni++) {
                int n = wn + ni*8 + qr;
                bf[ni][0] = Bs[buf][kk + qc    ][n];
                bf[ni][1] = Bs[buf][kk + qc + 4][n];
            }
            #pragma unroll
            for (int mi = 0; mi < 4; mi++)
                #pragma unroll
                for (int ni = 0; ni < 4; ni++)
                    mma8(acc[mi][ni], af[mi], bf[ni]);
        }

        if (more) {
            const int nb = buf ^ 1;
            uint4 u;
            u.x = f2tf(ra0.x); u.y = f2tf(ra0.y); u.z = f2tf(ra0.z); u.w = f2tf(ra0.w);
            *(uint4*)&As[nb][aRow][aK] = u;
            u.x = f2tf(ra1.x); u.y = f2tf(ra1.y); u.z = f2tf(ra1.z); u.w = f2tf(ra1.w);
            *(uint4*)&As[nb][aRow][aK + 4] = u;
            u.x = f2tf(rb0.x); u.y = f2tf(rb0.y); u.z = f2tf(rb0.z); u.w = f2tf(rb0.w);
            *(uint4*)&Bs[nb][bRow][bCol] = u;
            u.x = f2tf(rb1.x); u.y = f2tf(rb1.y); u.z = f2tf(rb1.z); u.w = f2tf(rb1.w);
            *(uint4*)&Bs[nb][bRow][bCol + 4] = u;
        }
        __syncthreads();
    }

    const int row0 = block_row*128 + wm;
    const int col0 = block_col*128 + wn;

    float cs[4][2], cq[4][2];
    #pragma unroll
    for (int ni = 0; ni < 4; ni++) {
        cs[ni][0] = cs[ni][1] = 0.f;
        cq[ni][0] = cq[ni][1] = 0.f;
    }

    #pragma unroll
    for (int mi = 0; mi < 4; mi++) {
        #pragma unroll
        for (int half = 0; half < 2; half++) {
            const int r = row0 + mi*16 + qr + half*8;
            #pragma unroll
            for (int ni = 0; ni < 4; ni++) {
                const int c = col0 + ni*8 + 2*qc;
                float v0 = acc[mi][ni][half*2 + 0];
                float v1 = acc[mi][ni][half*2 + 1];
                if (bias) { v0 += bias[c]; v1 += bias[c+1]; }
                if (res) {
                    float2 rv = *(const float2*)(res + (size_t)r*N + c);
                    v0 += rv.x; v1 += rv.y;
                }
                if (relu) { v0 = fmaxf(v0, 0.f); v1 = fmaxf(v1, 0.f); }
                if (ssum) {
                    cs[ni][0] += v0; cs[ni][1] += v1;
                    cq[ni][0] += v0*v0; cq[ni][1] += v1*v1;
                }
                *(float2*)(Cc + (size_t)r*N + c) = make_float2(v0, v1);
            }
        }
    }

    if (ssum) {
        #pragma unroll
        for (int ni = 0; ni < 4; ni++) {
            #pragma unroll
            for (int e = 0; e < 2; e++) {
                float s = cs[ni][e], q = cq[ni][e];
                #pragma unroll
                for (int off = 4; off < 32; off <<= 1) {
                    s += __shfl_xor_sync(0xffffffffu, s, off);
                    q += __shfl_xor_sync(0xffffffffu, q, off);
                }
                if (qr == 0) {
                    int c = col0 + ni*8 + 2*qc + e;
                    atomicAdd(&ssum[c], s);
                    atomicAdd(&ssq[c], q);
                }
            }
        }
    }
}

// ---------------- generic GEMM (Wo, MLP) ----------------
__global__ __launch_bounds__(256, 2)
void sgemm_kernel(const float* __restrict__ A, const float* __restrict__ Bm,
                  const float* __restrict__ bias, const float* __restrict__ res,
                  float* __restrict__ Cc, int N, int K, int relu,
                  float* ssum, float* ssq)
{
    __shared__ uint32_t As[2][128][TAPAD];
    __shared__ uint32_t Bs[2][16][TBPAD];
    mma_gemm_core(A, Bm, bias, res, Cc, N, K, blockIdx.y, blockIdx.x, relu,
                  ssum, ssq, As, Bs);
}

// ---------------- merged 5-way projection GEMM ----------------
struct P5 {
    const float* B[5];
    const float* bias[5];
    const float* res[5];
    float*       C[5];
};

__global__ __launch_bounds__(256, 2)
void proj_gemm_kernel(const float* __restrict__ A, P5 p)
{
    __shared__ uint32_t As[2][128][TAPAD];
    __shared__ uint32_t Bs[2][16][TBPAD];
    const int bw = blockIdx.x >> 1;
    const int bc = blockIdx.x & 1;
    mma_gemm_core(A, p.B[bw], p.bias[bw], p.res[bw], p.C[bw],
                  CCH, CCH, blockIdx.y, bc, 0, nullptr, nullptr, As, Bs);
}

// ---------------- edge scatter: agg[dst] += xWn[src] (vector red) ------
__global__ void scatter_kernel(const int* __restrict__ ei) {
    int t = blockIdx.x * blockDim.x + threadIdx.x;
    if (t >= EE*64) return;
    int e = t >> 6;
    int j = (t & 63) * 4;
    int src = ei[e];
    int dst = ei[EE + e];
    float4 mv = *(const float4*)(g_xWn + (size_t)src*CCH + j);
    float* p = g_agg + (size_t)dst*CCH + j;
    asm volatile("red.global.add.v4.f32 [%0], {%1,%2,%3,%4};"
                 :: "l"(p), "f"(mv.x), "f"(mv.y), "f"(mv.z), "f"(mv.w)
                 : "memory");
}

// ---------------- per-column stats (h1 = agg) -> slot 0 ----------------
__global__ void colstats_kernel(const float* __restrict__ X,
                                float* __restrict__ ssum, float* __restrict__ ssq) {
    int c = threadIdx.x;
    size_t r0 = (size_t)blockIdx.x * 16;
    float s = 0.f, q = 0.f;
    #pragma unroll
    for (int rr = 0; rr < 16; rr++) {
        float v = X[(r0 + rr)*CCH + c];
        s += v; q += v * v;
    }
    atomicAdd(&ssum[c], s);
    atomicAdd(&ssq[c], q);
}

// =======================================================================
// Attention: S = Q K^T (tf32 mma, Q a-frags hoisted in regs), P kept in
// registers (c-layout == bf16 a-layout), PV via bf16 m16n8k16 mma.
// No smem transpose of P, no cross-warp reductions. 2 syncs/chunk.
// grid: (N/128, H, B), 256 threads (8 warps, 16 q-rows each).
// =======================================================================
#define KB_WORDS (32*66)    // K b-frags (tf32): [8 ni * 4 ks][lane*2 + e]
#define VB_WORDS (16*66)    // V b-frags (bf16x2): [4 nf * 4 k16][lane*2 + reg]

__global__ __launch_bounds__(256, 2)
void attn_mma_kernel(const float* __restrict__ sph) {
    __shared__ uint32_t KB[KB_WORDS];
    __shared__ uint32_t VB[VB_WORDS];

    const int i0   = blockIdx.x * 128;
    const int h    = blockIdx.y;
    const int b    = blockIdx.z;
    const int tid  = threadIdx.x;
    const int lane = tid & 31;
    const int w    = tid >> 5;
    const int qr   = lane >> 2;
    const int qc   = lane & 3;
    const int m0   = w * 16;

    const size_t base = (size_t)b*NNODE*CCH + h*DKK;
    const float rscale = 0.17677669529663688f;  // 1/sqrt(32)

    // ---- hoist Q a-fragments (chunk-invariant) ----
    const float* q0 = g_q + base + (size_t)(i0 + m0 + qr)*CCH;      // row qr
    const float* q8 = q0 + 8*CCH;                                    // row qr+8
    uint32_t qa[4][4];
    #pragma unroll
    for (int ks = 0; ks < 4; ks++) {
        qa[ks][0] = f2tf(q0[ks*8 + qc]);
        qa[ks][1] = f2tf(q8[ks*8 + qc]);
        qa[ks][2] = f2tf(q0[ks*8 + qc + 4]);
        qa[ks][3] = f2tf(q8[ks*8 + qc + 4]);
    }

    float oc[4][4];
    #pragma unroll
    for (int a = 0; a < 4; a++)
        #pragma unroll
        for (int r = 0; r < 4; r++) oc[a][r] = 0.f;
    float rs0 = 0.f, rs1 = 0.f;

    const float* sph0 = sph + ((size_t)b*NNODE + i0 + m0 + qr)*NNODE;
    const float* sph8 = sph0 + 8*NNODE;

    // K pack slice: 64 rows * 8 groups = 512 / 256 threads = 2 reps
    // V pack slice: 32 row-pairs * 8 groups = 256 = 1 rep
    for (int jt = 0; jt < NNODE; jt += 64) {
        // ---- pack K (tf32 b-frags) and V (bf16x2 b-frags) ----
        #pragma unroll
        for (int rep = 0; rep < 2; rep++) {
            int idx = tid + rep*256;
            int j = idx >> 3, c4 = (idx & 7) * 4;
            float4 kv = *(const float4*)(g_k + base + (size_t)(jt + j)*CCH + c4);
            int ni = j >> 3, qrb = j & 7;
            int ks = c4 >> 3, e = (c4 >> 2) & 1;
            int wbase = (ni*4 + ks)*66 + e;
            KB[wbase + (qrb*4 + 0)*2] = f2tf(kv.x);
            KB[wbase + (qrb*4 + 1)*2] = f2tf(kv.y);
            KB[wbase + (qrb*4 + 2)*2] = f2tf(kv.z);
            KB[wbase + (qrb*4 + 3)*2] = f2tf(kv.w);
        }
        {
            int jp = tid >> 3, c4 = (tid & 7) * 4;
            float4 v0 = *(const float4*)(g_v + base + (size_t)(jt + 2*jp    )*CCH + c4);
            float4 v1 = *(const float4*)(g_v + base + (size_t)(jt + 2*jp + 1)*CCH + c4);
            int ksv = jp >> 3, reg = (jp >> 2) & 1, qcv = jp & 3;
            int nf = c4 >> 3, qv0 = c4 & 7;
            int wbase = (nf*4 + ksv)*66 + reg;
            VB[wbase + ((qv0 + 0)*4 + qcv)*2] = bf2(v0.x, v1.x);
            VB[wbase + ((qv0 + 1)*4 + qcv)*2] = bf2(v0.y, v1.y);
            VB[wbase + ((qv0 + 2)*4 + qcv)*2] = bf2(v0.z, v1.z);
            VB[wbase + ((qv0 + 3)*4 + qcv)*2] = bf2(v0.w, v1.w);
        }
        __syncthreads();

        // ---- S = Q K^T (tf32) ----
        float sc[8][4];
        #pragma unroll
        for (int ni = 0; ni < 8; ni++)
            #pragma unroll
            for (int r = 0; r < 4; r++) sc[ni][r] = 0.f;

        #pragma unroll
        for (int ks = 0; ks < 4; ks++) {
            #pragma unroll
            for (int ni = 0; ni < 8; ni++) {
                uint2 bfv = *(const uint2*)&KB[(ni*4 + ks)*66 + lane*2];
                uint32_t bf[2] = {bfv.x, bfv.y};
                mma8(sc[ni], qa[ks], bf);
            }
        }

        // ---- exp(sc * rscale * sph) in registers -> bf16x2 a-frags ----
        uint32_t pe[8][2];
        #pragma unroll
        for (int ni = 0; ni < 8; ni++) {
            float2 s0 = *(const float2*)(sph0 + jt + ni*8 + 2*qc);
            float2 s1 = *(const float2*)(sph8 + jt + ni*8 + 2*qc);
            float p0 = __expf(sc[ni][0] * rscale * s0.x);
            float p1 = __expf(sc[ni][1] * rscale * s0.y);
            float p2 = __expf(sc[ni][2] * rscale * s1.x);
            float p3 = __expf(sc[ni][3] * rscale * s1.y);
            rs0 += p0 + p1;
            rs1 += p2 + p3;
            pe[ni][0] = bf2(p0, p1);
            pe[ni][1] = bf2(p2, p3);
        }

        // ---- O += P V (bf16 m16n8k16) ----
        #pragma unroll
        for (int k16 = 0; k16 < 4; k16++) {
            uint32_t af[4] = { pe[2*k16][0], pe[2*k16][1],
                               pe[2*k16+1][0], pe[2*k16+1][1] };
            #pragma unroll
            for (int nf = 0; nf < 4; nf++) {
                uint2 bfv = *(const uint2*)&VB[(nf*4 + k16)*66 + lane*2];
                uint32_t bf[2] = {bfv.x, bfv.y};
                mma16bf(oc[nf], af, bf);
            }
        }
        __syncthreads();   // KB/VB free for next chunk's pack
    }

    // ---- rowsum reduce over the 4 qc lanes (full row within warp) ----
    rs0 += __shfl_xor_sync(0xffffffffu, rs0, 1);
    rs0 += __shfl_xor_sync(0xffffffffu, rs0, 2);
    rs1 += __shfl_xor_sync(0xffffffffu, rs1, 1);
    rs1 += __shfl_xor_sync(0xffffffffu, rs1, 2);
    const float inv0 = 1.f / rs0;
    const float inv1 = 1.f / rs1;

    // ---- write O (c-layout) ----
    float* o0 = g_o + base + (size_t)(i0 + m0 + qr)*CCH;
    float* o8 = o0 + 8*CCH;
    #pragma unroll
    for (int nf = 0; nf < 4; nf++) {
        const int d = nf*8 + 2*qc;
        *(float2*)(o0 + d) = make_float2(oc[nf][0]*inv0, oc[nf][1]*inv0);
        *(float2*)(o8 + d) = make_float2(oc[nf][2]*inv1, oc[nf][3]*inv1);
    }
}

// ---------------- out0 = BN1(h1=agg) + BN2(h2) ----------------
__global__ void bn_combine_kernel(const float* __restrict__ ga1, const float* __restrict__ be1,
                                  const float* __restrict__ ga2, const float* __restrict__ be2) {
    int idx = blockIdx.x * blockDim.x + threadIdx.x;
    if (idx >= BNT*CCH/4) return;
    int c0 = (idx << 2) & (CCH - 1);
    float4 a = ((const float4*)g_agg)[idx];
    float4 bb = ((const float4*)g_h2)[idx];
    float av[4] = {a.x, a.y, a.z, a.w};
    float bv[4] = {bb.x, bb.y, bb.z, bb.w};
    float ov[4];
    const float inv_n = 1.f / (float)BNT;
    #pragma unroll
    for (int j = 0; j < 4; j++) {
        int c = c0 + j;
        float m1 = g_ssum[0][c] * inv_n;
        float v1 = g_ssq[0][c] * inv_n - m1*m1;
        float i1 = rsqrtf(v1 + EPSB);
        float m2 = g_ssum[1][c] * inv_n;
        float v2 = g_ssq[1][c] * inv_n - m2*m2;
        float i2 = rsqrtf(v2 + EPSB);
        ov[j] = (av[j]-m1)*i1*ga1[c] + be1[c] + (bv[j]-m2)*i2*ga2[c] + be2[c];
    }
    ((float4*)g_out0)[idx] = make_float4(ov[0], ov[1], ov[2], ov[3]);
}

// ---------------- final BN3 -> output ----------------
__global__ void bn_final_kernel(const float* __restrict__ ga3, const float* __restrict__ be3,
                                float* __restrict__ out) {
    int idx = blockIdx.x * blockDim.x + threadIdx.x;
    if (idx >= BNT*CCH/4) return;
    int c0 = (idx << 2) & (CCH - 1);
    float4 a = ((const float4*)g_out1)[idx];
    float av[4] = {a.x, a.y, a.z, a.w};
    float ov[4];
    const float inv_n = 1.f / (float)BNT;
    #pragma unroll
    for (int j = 0; j < 4; j++) {
        int c = c0 + j;
        float m3 = g_ssum[2][c] * inv_n;
        float v3 = g_ssq[2][c] * inv_n - m3*m3;
        float i3 = rsqrtf(v3 + EPSB);
        ov[j] = (av[j]-m3)*i3*ga3[c] + be3[c];
    }
    ((float4*)out)[idx] = make_float4(ov[0], ov[1], ov[2], ov[3]);
}

// ---------------- launcher ----------------
extern "C" void kernel_launch(void* const* d_in, const int* in_sizes, int n_in,
                              void* d_out, int out_size) {
    const float* x    = (const float*)d_in[0];
    const int*   eidx = (const int*)d_in[1];
    const float* sph  = (const float*)d_in[2];
    const float* Wr   = (const float*)d_in[3];
    const float* Wn   = (const float*)d_in[4];
    const float* Wq   = (const float*)d_in[5];
    const float* bq   = (const float*)d_in[6];
    const float* Wk   = (const float*)d_in[7];
    const float* bk   = (const float*)d_in[8];
    const float* Wv   = (const float*)d_in[9];
    const float* bv   = (const float*)d_in[10];
    const float* Wo   = (const float*)d_in[11];
    const float* bo   = (const float*)d_in[12];
    const float* W1   = (const float*)d_in[13];
    const float* b1   = (const float*)d_in[14];
    const float* W2   = (const float*)d_in[15];
    const float* b2   = (const float*)d_in[16];
    const float* ga1  = (const float*)d_in[17];
    const float* be1  = (const float*)d_in[18];
    const float* ga2  = (const float*)d_in[19];
    const float* be2  = (const float*)d_in[20];
    const float* ga3  = (const float*)d_in[21];
    const float* be3  = (const float*)d_in[22];
    float* out = (float*)d_out;

    float *p_xWn, *p_agg, *p_q, *p_k, *p_v, *p_o, *p_h2, *p_out0, *p_hid, *p_out1;
    float *p_ssum, *p_ssq;
    cudaGetSymbolAddress((void**)&p_xWn,  g_xWn);
    cudaGetSymbolAddress((void**)&p_agg,  g_agg);
    cudaGetSymbolAddress((void**)&p_q,    g_q);
    cudaGetSymbolAddress((void**)&p_k,    g_k);
    cudaGetSymbolAddress((void**)&p_v,    g_v);
    cudaGetSymbolAddress((void**)&p_o,    g_o);
    cudaGetSymbolAddress((void**)&p_h2,   g_h2);
    cudaGetSymbolAddress((void**)&p_out0, g_out0);
    cudaGetSymbolAddress((void**)&p_hid,  g_hid);
    cudaGetSymbolAddress((void**)&p_out1, g_out1);
    cudaGetSymbolAddress((void**)&p_ssum, g_ssum);
    cudaGetSymbolAddress((void**)&p_ssq,  g_ssq);

    const int elem4_blocks = (BNT*CCH/4 + 255) / 256;    // 2048

    zero_stats_kernel<<<1, 256>>>();

    // merged projections: xWn, agg(=x@Wr+x), q, k, v in one launch
    P5 p5;
    p5.B[0] = Wn; p5.B[1] = Wr; p5.B[2] = Wq; p5.B[3] = Wk; p5.B[4] = Wv;
    p5.bias[0] = nullptr; p5.bias[1] = nullptr;
    p5.bias[2] = bq; p5.bias[3] = bk; p5.bias[4] = bv;
    p5.res[0] = nullptr; p5.res[1] = x; p5.res[2] = nullptr;
    p5.res[3] = nullptr; p5.res[4] = nullptr;
    p5.C[0] = p_xWn; p5.C[1] = p_agg; p5.C[2] = p_q; p5.C[3] = p_k; p5.C[4] = p_v;
    proj_gemm_kernel<<<dim3(10, BNT/128), 256>>>(x, p5);

    // edge aggregation on top of x@Wr + x
    scatter_kernel<<<EE*64/256, 256>>>(eidx);

    // h1 stats (slot 0)
    colstats_kernel<<<BNT/16, 256>>>(p_agg, p_ssum + 0*CCH, p_ssq + 0*CCH);

    // branch 2: attention + output projection (+x residual, fused h2 stats slot 1)
    attn_mma_kernel<<<dim3(NNODE/128, HH, BB), 256>>>(sph);
    sgemm_kernel<<<dim3(CCH/128, BNT/128), 256>>>(p_o, Wo, bo, x, p_h2, CCH, CCH, 0,
                                                  p_ssum + 1*CCH, p_ssq + 1*CCH);

    // combine BN branches
    bn_combine_kernel<<<elem4_blocks, 256>>>(ga1, be1, ga2, be2);

    // MLP (W2 gemm fuses out1 stats slot 2)
    sgemm_kernel<<<dim3(C2/128, BNT/128), 256>>>(p_out0, W1, b1, nullptr, p_hid, C2, CCH, 1,
                                                 nullptr, nullptr);
    sgemm_kernel<<<dim3(CCH/128, BNT/128), 256>>>(p_hid, W2, b2, p_out0, p_out1, CCH, C2, 0,
                                                  p_ssum + 2*CCH, p_ssq + 2*CCH);

    // final BN
    bn_final_kernel<<<elem4_blocks, 256>>>(ga3, be3, out);
}

// round 16
// speedup vs baseline: 1.0085x; 1.0034x over previous
#include <cuda_runtime.h>
#include <cstdint>

// ---------------- problem constants ----------------
#define BNT   8192      // B*N nodes
#define CCH   256       // channels
#define BB    8
#define NNODE 1024
#define HH    8
#define DKK   32
#define EE    131072
#define C2    512
#define EPSB  1e-5f

// ---------------- device scratch ----------------
__device__ float g_xWn [BNT*CCH];
__device__ float g_q   [BNT*CCH];
__device__ float g_k   [BNT*CCH];
__device__ float g_v   [BNT*CCH];
__device__ float g_agg [BNT*CCH];   // h1 = x@Wr + x + segsum
__device__ float g_o   [BNT*CCH];
__device__ float g_h2  [BNT*CCH];
__device__ float g_out0[BNT*CCH];
__device__ float g_hid [BNT*C2];
__device__ float g_out1[BNT*CCH];
__device__ float g_ssum[3][CCH];
__device__ float g_ssq [3][CCH];

// ---------------- zero stats ----------------
__global__ void zero_stats_kernel() {
    int c = threadIdx.x;
    #pragma unroll
    for (int s = 0; s < 3; s++) { g_ssum[s][c] = 0.f; g_ssq[s][c] = 0.f; }
}

// =======================================================================
// tf32 tensor-core GEMM: 128x128 block, BK=16, 256 threads (8 warps),
// warp tile 64x32 = 4x4 m16n8k8 mma. Double-buffered smem.
// Optional fused column stats (sum, sumsq) via shfl-reduce + atomics.
// =======================================================================
#define TAPAD 20
#define TBPAD 136

__device__ __forceinline__ uint32_t f2tf(float x) {
    uint32_t y;
    asm volatile("cvt.rna.tf32.f32 %0, %1;" : "=r"(y) : "f"(x));
    return y;
}

__device__ __forceinline__ uint32_t bf2(float lo, float hi) {
    uint32_t r;
    asm volatile("cvt.rn.bf16x2.f32 %0, %1, %2;" : "=r"(r) : "f"(hi), "f"(lo));
    return r;
}

__device__ __forceinline__ void mma8(float* d, const uint32_t* a, const uint32_t* b) {
    asm volatile(
        "mma.sync.aligned.m16n8k8.row.col.f32.tf32.tf32.f32 "
        "{%0,%1,%2,%3}, {%4,%5,%6,%7}, {%8,%9}, {%0,%1,%2,%3};\n"
        : "+f"(d[0]), "+f"(d[1]), "+f"(d[2]), "+f"(d[3])
        : "r"(a[0]), "r"(a[1]), "r"(a[2]), "r"(a[3]),
          "r"(b[0]), "r"(b[1]));
}

__device__ __forceinline__ void mma16bf(float* d, const uint32_t* a, const uint32_t* b) {
    asm volatile(
        "mma.sync.aligned.m16n8k16.row.col.f32.bf16.bf16.f32 "
        "{%0,%1,%2,%3}, {%4,%5,%6,%7}, {%8,%9}, {%0,%1,%2,%3};\n"
        : "+f"(d[0]), "+f"(d[1]), "+f"(d[2]), "+f"(d[3])
        : "r"(a[0]), "r"(a[1]), "r"(a[2]), "r"(a[3]),
          "r"(b[0]), "r"(b[1]));
}

__device__ __forceinline__ void mma_gemm_core(
    const float* __restrict__ A, const float* __restrict__ Bm,
    const float* __restrict__ bias, const float* __restrict__ res,
    float* __restrict__ Cc, int N, int K, int block_row, int block_col, int relu,
    float* __restrict__ ssum, float* __restrict__ ssq,
    uint32_t (*As)[128][TAPAD], uint32_t (*Bs)[16][TBPAD])
{
    const int tid  = threadIdx.x;
    const int lane = tid & 31;
    const int w    = tid >> 5;
    const int wm   = (w >> 2) * 64;
    const int wn   = (w & 3) * 32;
    const int qr   = lane >> 2;
    const int qc   = lane & 3;

    const int aRow = tid >> 1;
    const int aK   = (tid & 1) * 8;
    const int bRow = tid >> 4;
    const int bCol = (tid & 15) * 8;

    const float* Aptr = A + (size_t)(block_row*128) * K;
    const float* Bptr = Bm + block_col*128;

    float acc[4][4][4];
    #pragma unroll
    for (int mi = 0; mi < 4; mi++)
        #pragma unroll
        for (int ni = 0; ni < 4; ni++)
            #pragma unroll
            for (int r = 0; r < 4; r++) acc[mi][ni][r] = 0.f;

    const int nstages = K >> 4;
    float4 ra0, ra1, rb0, rb1;

    ra0 = *(const float4*)(Aptr + (size_t)aRow*K + aK);
    ra1 = *(const float4*)(Aptr + (size_t)aRow*K + aK + 4);
    rb0 = *(const float4*)(Bptr + (size_t)bRow*N + bCol);
    rb1 = *(const float4*)(Bptr + (size_t)bRow*N + bCol + 4);
    {
        uint4 u;
        u.x = f2tf(ra0.x); u.y = f2tf(ra0.y); u.z = f2tf(ra0.z); u.w = f2tf(ra0.w);
        *(uint4*)&As[0][aRow][aK] = u;
        u.x = f2tf(ra1.x); u.y = f2tf(ra1.y); u.z = f2tf(ra1.z); u.w = f2tf(ra1.w);
        *(uint4*)&As[0][aRow][aK + 4] = u;
        u.x = f2tf(rb0.x); u.y = f2tf(rb0.y); u.z = f2tf(rb0.z); u.w = f2tf(rb0.w);
        *(uint4*)&Bs[0][bRow][bCol] = u;
        u.x = f2tf(rb1.x); u.y = f2tf(rb1.y); u.z = f2tf(rb1.z); u.w = f2tf(rb1.w);
        *(uint4*)&Bs[0][bRow][bCol + 4] = u;
    }
    __syncthreads();

    for (int s = 0; s < nstages; s++) {
        const int buf = s & 1;
        const bool more = (s + 1 < nstages);
        if (more) {
            int k0 = (s + 1) << 4;
            ra0 = *(const float4*)(Aptr + (size_t)aRow*K + k0 + aK);
            ra1 = *(const float4*)(Aptr + (size_t)aRow*K + k0 + aK + 4);
            rb0 = *(const float4*)(Bptr + (size_t)(k0 + bRow)*N + bCol);
            rb1 = *(const float4*)(Bptr + (size_t)(k0 + bRow)*N + bCol + 4);
        }

        #pragma unroll
        for (int ks = 0; ks < 2; ks++) {
            const int kk = ks * 8;
            uint32_t af[4][4], bf[4][2];
            #pragma unroll
            for (int mi = 0; mi < 4; mi++) {
                int m = wm + mi*16 + qr;
                af[mi][0] = As[buf][m    ][kk + qc];
                af[mi][1] = As[buf][m + 8][kk + qc];
                af[mi][2] = As[buf][m    ][kk + qc + 4];
                af[mi][3] = As[buf][m + 8][kk + qc + 4];
            }
            #pragma unroll
            for (int ni = 0; ni < 4; ni++) {
                int n = wn + ni*8 + qr;
                bf[ni][0] = Bs[buf][kk + qc    ][n];
                bf[ni][1] = Bs[buf][kk + qc + 4][n];
            }
            #pragma unroll
            for (int mi = 0; mi < 4; mi++)
                #pragma unroll
                for (int ni = 0; ni < 4; ni++)
                    mma8(acc[mi][ni], af[mi], bf[ni]);
        }

        if (more) {
            const int nb = buf ^ 1;
            uint4 u;
            u.x = f2tf(ra0.x); u.y = f2tf(ra0.y); u.z = f2tf(ra0.z); u.w = f2tf(ra0.w);
            *(uint4*)&As[nb][aRow][aK] = u;
            u.x = f2tf(ra1.x); u.y = f2tf(ra1.y); u.z = f2tf(ra1.z); u.w = f2tf(ra1.w);
            *(uint4*)&As[nb][aRow][aK + 4] = u;
            u.x = f2tf(rb0.x); u.y = f2tf(rb0.y); u.z = f2tf(rb0.z); u.w = f2tf(rb0.w);
            *(uint4*)&Bs[nb][bRow][bCol] = u;
            u.x = f2tf(rb1.x); u.y = f2tf(rb1.y); u.z = f2tf(rb1.z); u.w = f2tf(rb1.w);
            *(uint4*)&Bs[nb][bRow][bCol + 4] = u;
        }
        __syncthreads();
    }

    const int row0 = block_row*128 + wm;
    const int col0 = block_col*128 + wn;

    float cs[4][2], cq[4][2];
    #pragma unroll
    for (int ni = 0; ni < 4; ni++) {
        cs[ni][0] = cs[ni][1] = 0.f;
        cq[ni][0] = cq[ni][1] = 0.f;
    }

    #pragma unroll
    for (int mi = 0; mi < 4; mi++) {
        #pragma unroll
        for (int half = 0; half < 2; half++) {
            const int r = row0 + mi*16 + qr + half*8;
            #pragma unroll
            for (int ni = 0; ni < 4; ni++) {
                const int c = col0 + ni*8 + 2*qc;
                float v0 = acc[mi][ni][half*2 + 0];
                float v1 = acc[mi][ni][half*2 + 1];
                if (bias) { v0 += bias[c]; v1 += bias[c+1]; }
                if (res) {
                    float2 rv = *(const float2*)(res + (size_t)r*N + c);
                    v0 += rv.x; v1 += rv.y;
                }
                if (relu) { v0 = fmaxf(v0, 0.f); v1 = fmaxf(v1, 0.f); }
                if (ssum) {
                    cs[ni][0] += v0; cs[ni][1] += v1;
                    cq[ni][0] += v0*v0; cq[ni][1] += v1*v1;
                }
                *(float2*)(Cc + (size_t)r*N + c) = make_float2(v0, v1);
            }
        }
    }

    if (ssum) {
        #pragma unroll
        for (int ni = 0; ni < 4; ni++) {
            #pragma unroll
            for (int e = 0; e < 2; e++) {
                float s = cs[ni][e], q = cq[ni][e];
                #pragma unroll
                for (int off = 4; off < 32; off <<= 1) {
                    s += __shfl_xor_sync(0xffffffffu, s, off);
                    q += __shfl_xor_sync(0xffffffffu, q, off);
                }
                if (qr == 0) {
                    int c = col0 + ni*8 + 2*qc + e;
                    atomicAdd(&ssum[c], s);
                    atomicAdd(&ssq[c], q);
                }
            }
        }
    }
}

// ---------------- generic GEMM (Wo, MLP) ----------------
__global__ __launch_bounds__(256, 2)
void sgemm_kernel(const float* __restrict__ A, const float* __restrict__ Bm,
                  const float* __restrict__ bias, const float* __restrict__ res,
                  float* __restrict__ Cc, int N, int K, int relu,
                  float* ssum, float* ssq)
{
    __shared__ uint32_t As[2][128][TAPAD];
    __shared__ uint32_t Bs[2][16][TBPAD];
    mma_gemm_core(A, Bm, bias, res, Cc, N, K, blockIdx.y, blockIdx.x, relu,
                  ssum, ssq, As, Bs);
}

// ---------------- merged 5-way projection GEMM ----------------
struct P5 {
    const float* B[5];
    const float* bias[5];
    const float* res[5];
    float*       C[5];
};

__global__ __launch_bounds__(256, 2)
void proj_gemm_kernel(const float* __restrict__ A, P5 p)
{
    __shared__ uint32_t As[2][128][TAPAD];
    __shared__ uint32_t Bs[2][16][TBPAD];
    const int bw = blockIdx.x >> 1;
    const int bc = blockIdx.x & 1;
    mma_gemm_core(A, p.B[bw], p.bias[bw], p.res[bw], p.C[bw],
                  CCH, CCH, blockIdx.y, bc, 0, nullptr, nullptr, As, Bs);
}

// ---------------- edge scatter: agg[dst] += xWn[src] (vector red) ------
__global__ void scatter_kernel(const int* __restrict__ ei) {
    int t = blockIdx.x * blockDim.x + threadIdx.x;
    if (t >= EE*64) return;
    int e = t >> 6;
    int j = (t & 63) * 4;
    int src = ei[e];
    int dst = ei[EE + e];
    float4 mv = *(const float4*)(g_xWn + (size_t)src*CCH + j);
    float* p = g_agg + (size_t)dst*CCH + j;
    asm volatile("red.global.add.v4.f32 [%0], {%1,%2,%3,%4};"
                 :: "l"(p), "f"(mv.x), "f"(mv.y), "f"(mv.z), "f"(mv.w)
                 : "memory");
}

// ---------------- per-column stats (h1 = agg) -> slot 0 ----------------
__global__ void colstats_kernel(const float* __restrict__ X,
                                float* __restrict__ ssum, float* __restrict__ ssq) {
    int c = threadIdx.x;
    size_t r0 = (size_t)blockIdx.x * 16;
    float s = 0.f, q = 0.f;
    #pragma unroll
    for (int rr = 0; rr < 16; rr++) {
        float v = X[(r0 + rr)*CCH + c];
        s += v; q += v * v;
    }
    atomicAdd(&ssum[c], s);
    atomicAdd(&ssq[c], q);
}

// =======================================================================
// Attention: S = Q K^T (tf32 mma, Q a-frags hoisted in regs), P kept in
// registers (c-layout == bf16 a-layout), PV via bf16 m16n8k16 mma.
// No smem transpose of P, no cross-warp reductions. 2 syncs/chunk.
// grid: (N/128, H, B), 256 threads (8 warps, 16 q-rows each).
// =======================================================================
#define KB_WORDS (32*66)    // K b-frags (tf32): [8 ni * 4 ks][lane*2 + e]
#define VB_WORDS (16*66)    // V b-frags (bf16x2): [4 nf * 4 k16][lane*2 + reg]

__global__ __launch_bounds__(256, 2)
void attn_mma_kernel(const float* __restrict__ sph) {
    __shared__ uint32_t KB[KB_WORDS];
    __shared__ uint32_t VB[VB_WORDS];

    const int i0   = blockIdx.x * 128;
    const int h    = blockIdx.y;
    const int b    = blockIdx.z;
    const int tid  = threadIdx.x;
    const int lane = tid & 31;
    const int w    = tid >> 5;
    const int qr   = lane >> 2;
    const int qc   = lane & 3;
    const int m0   = w * 16;

    const size_t base = (size_t)b*NNODE*CCH + h*DKK;
    const float rscale = 0.17677669529663688f;  // 1/sqrt(32)

    // ---- hoist Q a-fragments (chunk-invariant) ----
    const float* q0 = g_q + base + (size_t)(i0 + m0 + qr)*CCH;      // row qr
    const float* q8 = q0 + 8*CCH;                                    // row qr+8
    uint32_t qa[4][4];
    #pragma unroll
    for (int ks = 0; ks < 4; ks++) {
        qa[ks][0] = f2tf(q0[ks*8 + qc]);
        qa[ks][1] = f2tf(q8[ks*8 + qc]);
        qa[ks][2] = f2tf(q0[ks*8 + qc + 4]);
        qa[ks][3] = f2tf(q8[ks*8 + qc + 4]);
    }

    float oc[4][4];
    #pragma unroll
    for (int a = 0; a < 4; a++)
        #pragma unroll
        for (int r = 0; r < 4; r++) oc[a][r] = 0.f;
    float rs0 = 0.f, rs1 = 0.f;

    const float* sph0 = sph + ((size_t)b*NNODE + i0 + m0 + qr)*NNODE;
    const float* sph8 = sph0 + 8*NNODE;

    // K pack slice: 64 rows * 8 groups = 512 / 256 threads = 2 reps
    // V pack slice: 32 row-pairs * 8 groups = 256 = 1 rep
    for (int jt = 0; jt < NNODE; jt += 64) {
        // ---- pack K (tf32 b-frags) and V (bf16x2 b-frags) ----
        #pragma unroll
        for (int rep = 0; rep < 2; rep++) {
            int idx = tid + rep*256;
            int j = idx >> 3, c4 = (idx & 7) * 4;
            float4 kv = *(const float4*)(g_k + base + (size_t)(jt + j)*CCH + c4);
            int ni = j >> 3, qrb = j & 7;
            int ks = c4 >> 3, e = (c4 >> 2) & 1;
            int wbase = (ni*4 + ks)*66 + e;
            KB[wbase + (qrb*4 + 0)*2] = f2tf(kv.x);
            KB[wbase + (qrb*4 + 1)*2] = f2tf(kv.y);
            KB[wbase + (qrb*4 + 2)*2] = f2tf(kv.z);
            KB[wbase + (qrb*4 + 3)*2] = f2tf(kv.w);
        }
        {
            int jp = tid >> 3, c4 = (tid & 7) * 4;
            float4 v0 = *(const float4*)(g_v + base + (size_t)(jt + 2*jp    )*CCH + c4);
            float4 v1 = *(const float4*)(g_v + base + (size_t)(jt + 2*jp + 1)*CCH + c4);
            int ksv = jp >> 3, reg = (jp >> 2) & 1, qcv = jp & 3;
            int nf = c4 >> 3, qv0 = c4 & 7;
            int wbase = (nf*4 + ksv)*66 + reg;
            VB[wbase + ((qv0 + 0)*4 + qcv)*2] = bf2(v0.x, v1.x);
            VB[wbase + ((qv0 + 1)*4 + qcv)*2] = bf2(v0.y, v1.y);
            VB[wbase + ((qv0 + 2)*4 + qcv)*2] = bf2(v0.z, v1.z);
            VB[wbase + ((qv0 + 3)*4 + qcv)*2] = bf2(v0.w, v1.w);
        }
        __syncthreads();

        // ---- S = Q K^T (tf32) ----
        float sc[8][4];
        #pragma unroll
        for (int ni = 0; ni < 8; ni++)
            #pragma unroll
            for (int r = 0; r < 4; r++) sc[ni][r] = 0.f;

        #pragma unroll
        for (int ks = 0; ks < 4; ks++) {
            #pragma unroll
            for (int ni = 0; ni < 8; ni++) {
                uint2 bfv = *(const uint2*)&KB[(ni*4 + ks)*66 + lane*2];
                uint32_t bf[2] = {bfv.x, bfv.y};
                mma8(sc[ni], qa[ks], bf);
            }
        }

        // ---- exp(sc * rscale * sph) in registers -> bf16x2 a-frags ----
        uint32_t pe[8][2];
        #pragma unroll
        for (int ni = 0; ni < 8; ni++) {
            float2 s0 = *(const float2*)(sph0 + jt + ni*8 + 2*qc);
            float2 s1 = *(const float2*)(sph8 + jt + ni*8 + 2*qc);
            float p0 = __expf(sc[ni][0] * rscale * s0.x);
            float p1 = __expf(sc[ni][1] * rscale * s0.y);
            float p2 = __expf(sc[ni][2] * rscale * s1.x);
            float p3 = __expf(sc[ni][3] * rscale * s1.y);
            rs0 += p0 + p1;
            rs1 += p2 + p3;
            pe[ni][0] = bf2(p0, p1);
            pe[ni][1] = bf2(p2, p3);
        }

        // ---- O += P V (bf16 m16n8k16) ----
        #pragma unroll
        for (int k16 = 0; k16 < 4; k16++) {
            uint32_t af[4] = { pe[2*k16][0], pe[2*k16][1],
                               pe[2*k16+1][0], pe[2*k16+1][1] };
            #pragma unroll
            for (int nf = 0; nf < 4; nf++) {
                uint2 bfv = *(const uint2*)&VB[(nf*4 + k16)*66 + lane*2];
                uint32_t bf[2] = {bfv.x, bfv.y};
                mma16bf(oc[nf], af, bf);
            }
        }
        __syncthreads();   // KB/VB free for next chunk's pack
    }

    // ---- rowsum reduce over the 4 qc lanes (full row within warp) ----
    rs0 += __shfl_xor_sync(0xffffffffu, rs0, 1);
    rs0 += __shfl_xor_sync(0xffffffffu, rs0, 2);
    rs1 += __shfl_xor_sync(0xffffffffu, rs1, 1);
    rs1 += __shfl_xor_sync(0xffffffffu, rs1, 2);
    const float inv0 = 1.f / rs0;
    const float inv1 = 1.f / rs1;

    // ---- write O (c-layout) ----
    float* o0 = g_o + base + (size_t)(i0 + m0 + qr)*CCH;
    float* o8 = o0 + 8*CCH;
    #pragma unroll
    for (int nf = 0; nf < 4; nf++) {
        const int d = nf*8 + 2*qc;
        *(float2*)(o0 + d) = make_float2(oc[nf][0]*inv0, oc[nf][1]*inv0);
        *(float2*)(o8 + d) = make_float2(oc[nf][2]*inv1, oc[nf][3]*inv1);
    }
}

// ---------------- out0 = BN1(h1=agg) + BN2(h2) ----------------
__global__ void bn_combine_kernel(const float* __restrict__ ga1, const float* __restrict__ be1,
                                  const float* __restrict__ ga2, const float* __restrict__ be2) {
    int idx = blockIdx.x * blockDim.x + threadIdx.x;
    if (idx >= BNT*CCH/4) return;
    int c0 = (idx << 2) & (CCH - 1);
    float4 a = ((const float4*)g_agg)[idx];
    float4 bb = ((const float4*)g_h2)[idx];
    float av[4] = {a.x, a.y, a.z, a.w};
    float bv[4] = {bb.x, bb.y, bb.z, bb.w};
    float ov[4];
    const float inv_n = 1.f / (float)BNT;
    #pragma unroll
    for (int j = 0; j < 4; j++) {
        int c = c0 + j;
        float m1 = g_ssum[0][c] * inv_n;
        float v1 = g_ssq[0][c] * inv_n - m1*m1;
        float i1 = rsqrtf(v1 + EPSB);
        float m2 = g_ssum[1][c] * inv_n;
        float v2 = g_ssq[1][c] * inv_n - m2*m2;
        float i2 = rsqrtf(v2 + EPSB);
        ov[j] = (av[j]-m1)*i1*ga1[c] + be1[c] + (bv[j]-m2)*i2*ga2[c] + be2[c];
    }
    ((float4*)g_out0)[idx] = make_float4(ov[0], ov[1], ov[2], ov[3]);
}

// ---------------- final BN3 -> output ----------------
__global__ void bn_final_kernel(const float* __restrict__ ga3, const float* __restrict__ be3,
                                float* __restrict__ out) {
    int idx = blockIdx.x * blockDim.x + threadIdx.x;
    if (idx >= BNT*CCH/4) return;
    int c0 = (idx << 2) & (CCH - 1);
    float4 a = ((const float4*)g_out1)[idx];
    float av[4] = {a.x, a.y, a.z, a.w};
    float ov[4];
    const float inv_n = 1.f / (float)BNT;
    #pragma unroll
    for (int j = 0; j < 4; j++) {
        int c = c0 + j;
        float m3 = g_ssum[2][c] * inv_n;
        float v3 = g_ssq[2][c] * inv_n - m3*m3;
        float i3 = rsqrtf(v3 + EPSB);
        ov[j] = (av[j]-m3)*i3*ga3[c] + be3[c];
    }
    ((float4*)out)[idx] = make_float4(ov[0], ov[1], ov[2], ov[3]);
}

// ---------------- launcher ----------------
extern "C" void kernel_launch(void* const* d_in, const int* in_sizes, int n_in,
                              void* d_out, int out_size) {
    const float* x    = (const float*)d_in[0];
    const int*   eidx = (const int*)d_in[1];
    const float* sph  = (const float*)d_in[2];
    const float* Wr   = (const float*)d_in[3];
    const float* Wn   = (const float*)d_in[4];
    const float* Wq   = (const float*)d_in[5];
    const float* bq   = (const float*)d_in[6];
    const float* Wk   = (const float*)d_in[7];
    const float* bk   = (const float*)d_in[8];
    const float* Wv   = (const float*)d_in[9];
    const float* bv   = (const float*)d_in[10];
    const float* Wo   = (const float*)d_in[11];
    const float* bo   = (const float*)d_in[12];
    const float* W1   = (const float*)d_in[13];
    const float* b1   = (const float*)d_in[14];
    const float* W2   = (const float*)d_in[15];
    const float* b2   = (const float*)d_in[16];
    const float* ga1  = (const float*)d_in[17];
    const float* be1  = (const float*)d_in[18];
    const float* ga2  = (const float*)d_in[19];
    const float* be2  = (const float*)d_in[20];
    const float* ga3  = (const float*)d_in[21];
    const float* be3  = (const float*)d_in[22];
    float* out = (float*)d_out;

    float *p_xWn, *p_agg, *p_q, *p_k, *p_v, *p_o, *p_h2, *p_out0, *p_hid, *p_out1;
    float *p_ssum, *p_ssq;
    cudaGetSymbolAddress((void**)&p_xWn,  g_xWn);
    cudaGetSymbolAddress((void**)&p_agg,  g_agg);
    cudaGetSymbolAddress((void**)&p_q,    g_q);
    cudaGetSymbolAddress((void**)&p_k,    g_k);
    cudaGetSymbolAddress((void**)&p_v,    g_v);
    cudaGetSymbolAddress((void**)&p_o,    g_o);
    cudaGetSymbolAddress((void**)&p_h2,   g_h2);
    cudaGetSymbolAddress((void**)&p_out0, g_out0);
    cudaGetSymbolAddress((void**)&p_hid,  g_hid);
    cudaGetSymbolAddress((void**)&p_out1, g_out1);
    cudaGetSymbolAddress((void**)&p_ssum, g_ssum);
    cudaGetSymbolAddress((void**)&p_ssq,  g_ssq);

    const int elem4_blocks = (BNT*CCH/4 + 255) / 256;    // 2048

    zero_stats_kernel<<<1, 256>>>();

    // merged projections: xWn, agg(=x@Wr+x), q, k, v in one launch
    P5 p5;
    p5.B[0] = Wn; p5.B[1] = Wr; p5.B[2] = Wq; p5.B[3] = Wk; p5.B[4] = Wv;
    p5.bias[0] = nullptr; p5.bias[1] = nullptr;
    p5.bias[2] = bq; p5.bias[3] = bk; p5.bias[4] = bv;
    p5.res[0] = nullptr; p5.res[1] = x; p5.res[2] = nullptr;
    p5.res[3] = nullptr; p5.res[4] = nullptr;
    p5.C[0] = p_xWn; p5.C[1] = p_agg; p5.C[2] = p_q; p5.C[3] = p_k; p5.C[4] = p_v;
    proj_gemm_kernel<<<dim3(10, BNT/128), 256>>>(x, p5);

    // edge aggregation on top of x@Wr + x
    scatter_kernel<<<EE*64/256, 256>>>(eidx);

    // h1 stats (slot 0)
    colstats_kernel<<<BNT/16, 256>>>(p_agg, p_ssum + 0*CCH, p_ssq + 0*CCH);

    // branch 2: attention + output projection (+x residual, fused h2 stats slot 1)
    attn_mma_kernel<<<dim3(NNODE/128, HH, BB), 256>>>(sph);
    sgemm_kernel<<<dim3(CCH/128, BNT/128), 256>>>(p_o, Wo, bo, x, p_h2, CCH, CCH, 0,
                                                  p_ssum + 1*CCH, p_ssq + 1*CCH);

    // combine BN branches
    bn_combine_kernel<<<elem4_blocks, 256>>>(ga1, be1, ga2, be2);

    // MLP (W2 gemm fuses out1 stats slot 2)
    sgemm_kernel<<<dim3(C2/128, BNT/128), 256>>>(p_out0, W1, b1, nullptr, p_hid, C2, CCH, 1,
                                                 nullptr, nullptr);
    sgemm_kernel<<<dim3(CCH/128, BNT/128), 256>>>(p_hid, W2, b2, p_out0, p_out1, CCH, C2, 0,
                                                  p_ssum + 2*CCH, p_ssq + 2*CCH);

    // final BN
    bn_final_kernel<<<elem4_blocks, 256>>>(ga3, be3, out);
}